// round 15
// baseline (speedup 1.0000x reference)
#include <cuda_runtime.h>
#include <cuda_bf16.h>
#include <cstdint>
#include <math.h>

#define EPS   1e-5f
#define BB    2
#define NN    512
#define DD    64

typedef unsigned long long ull;
typedef unsigned int u32;

// ---------------- device scratch ----------------
__device__ __align__(16) float g_U   [BB*NN*128];
__device__ __align__(16) float g_V   [BB*NN*128];
__device__ __align__(16) float g_nfn [BB*NN*DD];
__device__ __align__(16) float g_W1t [128*128];
__device__ __align__(16) float g_Vb1 [128];
__device__ __align__(16) uint4 g_W2f [8*8*32];
__device__ __align__(16) uint4 g_W3f [4*4*32];
__device__ float g_c2[64], g_c3[32], g_w4[32], g_b4s;
__device__ __align__(16) float g_L   [BB*NN*NN];
__device__ int   g_active[BB];

// ---------------- helpers ----------------
__device__ __forceinline__ u32 pk(float e0, float e1) {
    u32 r; asm("cvt.rn.bf16x2.f32 %0, %1, %2;" : "=r"(r) : "f"(e1), "f"(e0)); return r;
}
__device__ __forceinline__ u32 pk_res(float e0, float e1, u32 h) {
    float r0 = __uint_as_float(h << 16);
    float r1 = __uint_as_float(h & 0xffff0000u);
    return pk(e0 - r0, e1 - r1);
}
__device__ __forceinline__ void mma16(float c[4], u32 a0, u32 a1, u32 a2, u32 a3,
                                      u32 b0, u32 b1) {
    asm("mma.sync.aligned.m16n8k16.row.col.f32.bf16.bf16.f32 "
        "{%0,%1,%2,%3}, {%4,%5,%6,%7}, {%8,%9}, {%0,%1,%2,%3};"
        : "+f"(c[0]), "+f"(c[1]), "+f"(c[2]), "+f"(c[3])
        : "r"(a0), "r"(a1), "r"(a2), "r"(a3), "r"(b0), "r"(b1));
}
__device__ __forceinline__ u32 s2u(const void* p) {
    u32 a;
    asm("{ .reg .u64 t; cvta.to.shared.u64 t, %1; cvt.u32.u64 %0, t; }" : "=r"(a) : "l"(p));
    return a;
}
__device__ __forceinline__ void cp16(u32 dst, const void* src) {
    asm volatile("cp.async.ca.shared.global [%0], [%1], 16;"
                 :: "r"(dst), "l"(__cvta_generic_to_global(src)) : "memory");
}
#define CP_COMMIT() asm volatile("cp.async.commit_group;" ::: "memory")
#define CP_WAIT(n)  asm volatile("cp.async.wait_group %0;" :: "n"(n) : "memory")

// ---------------- smem layout for k_main (bytes) ----------------
#define OFF_W2F  0          /* 32768 */
#define OFF_W3F  32768      /* 8192 */
#define OFF_US   40960      /* 3 x 4096 (8*128 f32)  */
#define OFF_VS   53248      /* 3 x 8448 (16*132 f32) */
#define OFF_C2   78592      /* 256 */
#define OFF_C3   78848      /* 128 */
#define OFF_W4   78976      /* 128 */
#define OFF_B4   79104      /* 4 */
#define SMEM_MM  79120

// ---------------- smem layout for k_epi (bytes) ----------------
#define EOFF_NFIT  0                    /* 64*68 f32 = 17408 B */
#define EOFF_NFJT  17408
#define EOFF_LIJ   34816
#define EOFF_LJIT  52224
#define EOFF_MI    69632               /* 64 ints */
#define EOFF_MJ    69888
#define EOFF_ACT   70144
#define SMEM_EPI   70160

// ---------------- setup: W1 transpose+fold, frag packing, consts, active ---
__global__ void k_setup(const float* __restrict__ W1, const float* __restrict__ b1,
                        const float* __restrict__ g1, const float* __restrict__ be1,
                        const float* __restrict__ m1, const float* __restrict__ v1,
                        const float* __restrict__ W2, const float* __restrict__ b2,
                        const float* __restrict__ g2, const float* __restrict__ be2,
                        const float* __restrict__ m2, const float* __restrict__ v2,
                        const float* __restrict__ W3, const float* __restrict__ b3,
                        const float* __restrict__ g3, const float* __restrict__ be3,
                        const float* __restrict__ m3, const float* __restrict__ v3,
                        const float* __restrict__ W4, const float* __restrict__ b4,
                        const int* __restrict__ masks) {
    int t = threadIdx.x;
    int bid = blockIdx.x;
    if (bid < 16) {
        __shared__ float tile[32][33];
        int ti = bid >> 2, tj = bid & 3;
        int tx = t & 31, ty = t >> 5;
        #pragma unroll
        for (int r = 0; r < 4; r++) {
            int o = ti * 32 + ty + 8 * r, in = tj * 32 + tx;
            tile[ty + 8 * r][tx] = W1[o * 128 + in];
        }
        __syncthreads();
        int o2 = ti * 32 + tx;
        float s1 = g1[o2] * rsqrtf(v1[o2] + EPS);
        #pragma unroll
        for (int r = 0; r < 4; r++) {
            int in2 = tj * 32 + ty + 8 * r;
            g_W1t[in2 * 128 + o2] = tile[tx][ty + 8 * r] * s1;
        }
        return;
    }
    if (bid < 24) {
        int fb = bid - 16;
        int idx = fb * 256 + t;
        {
            int ks = idx >> 8, nt = (idx >> 5) & 7, l = idx & 31;
            int n = 8 * nt + (l >> 2), k0 = 16 * ks + 2 * (l & 3);
            float s = g2[n] * rsqrtf(v2[n] + EPS);
            float w00 = W2[n * 128 + k0] * s,     w01 = W2[n * 128 + k0 + 1] * s;
            float w10 = W2[n * 128 + k0 + 8] * s, w11 = W2[n * 128 + k0 + 9] * s;
            u32 bh0 = pk(w00, w01), bh1 = pk(w10, w11);
            g_W2f[idx] = make_uint4(bh0, bh1, pk_res(w00, w01, bh0), pk_res(w10, w11, bh1));
        }
        if (idx < 4 * 4 * 32) {
            int ks = idx >> 7, nt = (idx >> 5) & 3, l = idx & 31;
            int n = 8 * nt + (l >> 2), k0 = 16 * ks + 2 * (l & 3);
            float s = g3[n] * rsqrtf(v3[n] + EPS);
            float w00 = W3[n * 64 + k0] * s,     w01 = W3[n * 64 + k0 + 1] * s;
            float w10 = W3[n * 64 + k0 + 8] * s, w11 = W3[n * 64 + k0 + 9] * s;
            u32 bh0 = pk(w00, w01), bh1 = pk(w10, w11);
            g_W3f[idx] = make_uint4(bh0, bh1, pk_res(w00, w01, bh0), pk_res(w10, w11, bh1));
        }
        return;
    }
    if (bid == 24) {
        if (t < 128) {
            float s1 = g1[t] * rsqrtf(v1[t] + EPS);
            g_Vb1[t] = (b1[t] - m1[t]) * s1 + be1[t];
        } else if (t < 192) {
            int o = t - 128;
            float s = g2[o] * rsqrtf(v2[o] + EPS);
            g_c2[o] = (b2[o] - m2[o]) * s + be2[o];
        } else if (t < 224) {
            int o = t - 192;
            float s = g3[o] * rsqrtf(v3[o] + EPS);
            g_c3[o] = (b3[o] - m3[o]) * s + be3[o];
        } else {
            g_w4[t - 224] = W4[t - 224];
        }
        if (t == 0) g_b4s = b4[0];
        return;
    }
    {
        __shared__ int cnt[BB];
        if (t < BB) cnt[t] = 0;
        __syncthreads();
        for (int idx = t; idx < BB * NN; idx += 256)
            if (masks[idx] != 0) atomicAdd(&cnt[idx / NN], 1);
        __syncthreads();
        if (t < BB) g_active[t] = (cnt[t] > 1) ? 1 : 0;
    }
}

// ---------------- nodes: batched 8 nodes/block, W1t reuse x8 ----------------
__global__ __launch_bounds__(128)
void k_nodes(const float* __restrict__ f) {
    __shared__ float fs[8][DD];
    __shared__ float sinv[8];
    int nb = blockIdx.x * 8;
    int t = threadIdx.x;
    {
        int n = t >> 4, c4 = (t & 15) * 4;
        float4 x = *(const float4*)&f[((size_t)nb + n) * DD + c4];
        *(float4*)&fs[n][c4] = x;
    }
    __syncthreads();
    {
        int wid = t >> 5, l = t & 31;
        int n0 = 2 * wid, n1 = n0 + 1;
        float s0 = fs[n0][l] * fs[n0][l] + fs[n0][l + 32] * fs[n0][l + 32];
        float s1 = fs[n1][l] * fs[n1][l] + fs[n1][l + 32] * fs[n1][l + 32];
        #pragma unroll
        for (int d = 16; d >= 1; d >>= 1) {
            s0 += __shfl_xor_sync(0xffffffffu, s0, d);
            s1 += __shfl_xor_sync(0xffffffffu, s1, d);
        }
        if (l == 0) {
            sinv[n0] = 1.f / fmaxf(sqrtf(s0), 1e-12f);
            sinv[n1] = 1.f / fmaxf(sqrtf(s1), 1e-12f);
        }
    }
    __syncthreads();
    #pragma unroll
    for (int it = 0; it < 4; it++) {
        int idx = t + it * 128;
        int n = idx >> 6, d = idx & 63;
        g_nfn[((size_t)nb + n) * DD + d] = fs[n][d] * sinv[n];
    }

    float u[8], vv[8];
    #pragma unroll
    for (int n = 0; n < 8; n++) { u[n] = 0.f; vv[n] = 0.f; }
    #pragma unroll 4
    for (int d = 0; d < DD; d++) {
        float wu = g_W1t[d * 128 + t];
        float wvv = g_W1t[(d + DD) * 128 + t];
        #pragma unroll
        for (int n = 0; n < 8; n++) {
            float fd = fs[n][d];
            u[n]  += wu * fd;
            vv[n] += wvv * fd;
        }
    }
    float vb = g_Vb1[t];
    #pragma unroll
    for (int n = 0; n < 8; n++) {
        g_U[((size_t)nb + n) * 128 + t] = u[n];
        g_V[((size_t)nb + n) * 128 + t] = vv[n] + vb;
    }
}

// ---------------- main: fused MLP via mma.sync bf16 k16, triple-buffered ---
__global__ __launch_bounds__(256, 2)
void k_main_mma() {
    extern __shared__ __align__(16) char sm[];
    uint4* W2s = (uint4*)(sm + OFF_W2F);
    uint4* W3s = (uint4*)(sm + OFF_W3F);
    float* c2s = (float*)(sm + OFF_C2);
    float* c3s = (float*)(sm + OFF_C3);
    float* w4s = (float*)(sm + OFF_W4);
    float* b4s = (float*)(sm + OFF_B4);

    u32 smb = s2u(sm);
    int t = threadIdx.x;
    int w = t >> 5, l = t & 31;
    int tg = l & 3, gid = l >> 2;

    {
        const uint4* s4 = (const uint4*)g_W2f;
        for (int i = t; i < 8 * 8 * 32; i += 256) W2s[i] = s4[i];
        const uint4* s3 = (const uint4*)g_W3f;
        for (int i = t; i < 4 * 4 * 32; i += 256) W3s[i] = s3[i];
        if (t < 64) c2s[t] = g_c2[t];
        if (t < 32) { c3s[t] = g_c3[t]; w4s[t] = g_w4[t]; }
        if (t == 0) b4s[0] = g_b4s;
    }

    const int NT = BB * (NN / 8) * (NN / 16);
    const int gsz = gridDim.x;

    auto stage = [&](int tile, int buf) {
        int b   = tile >> 11;
        int rem = tile & 2047;
        int i0  = (rem >> 5) << 3;
        int j0  = (rem & 31) << 4;
        cp16(smb + OFF_US + buf * 4096 + t * 16,
             (const char*)&g_U[((size_t)b * NN + i0) * 128] + t * 16);
        #pragma unroll
        for (int q = 0; q < 2; q++) {
            int c = t + q * 256;
            int jj = c >> 5, kq = c & 31;
            cp16(smb + OFF_VS + buf * 8448 + (jj * 132 + kq * 4) * 4,
                 &g_V[((size_t)b * NN + j0 + jj) * 128 + kq * 4]);
        }
        CP_COMMIT();
    };

    int first = blockIdx.x;
    if (first < NT) stage(first, 0);

    int pidx = 0;
    for (int tile = first; tile < NT; tile += gsz) {
        int nxt = tile + gsz;
        int nbuf = (pidx == 2) ? 0 : pidx + 1;
        if (nxt < NT) { stage(nxt, nbuf); CP_WAIT(1); }
        else          { CP_WAIT(0); }
        __syncthreads();

        float* Us = (float*)(sm + OFF_US + pidx * 4096);
        float* Vs = (float*)(sm + OFF_VS + pidx * 8448);
        pidx = nbuf;

        int b   = tile >> 11;
        int rem = tile & 2047;
        int i0  = (rem >> 5) << 3;
        int j0  = (rem & 31) << 4;

        float cA[8][4];
        #pragma unroll
        for (int nt = 0; nt < 8; nt++)
            #pragma unroll
            for (int q = 0; q < 4; q++) cA[nt][q] = 0.f;

        const float* urow = &Us[w * 128];
        #pragma unroll
        for (int ks = 0; ks < 8; ks++) {
            int k0 = 16 * ks + 2 * tg;
            float2 uA  = *(const float2*)&urow[k0];
            float2 uB  = *(const float2*)&urow[k0 + 8];
            float2 v0A = *(const float2*)&Vs[gid * 132 + k0];
            float2 v1A = *(const float2*)&Vs[(gid + 8) * 132 + k0];
            float2 v0B = *(const float2*)&Vs[gid * 132 + k0 + 8];
            float2 v1B = *(const float2*)&Vs[(gid + 8) * 132 + k0 + 8];
            float e00 = fmaxf(uA.x + v0A.x, 0.f), e01 = fmaxf(uA.y + v0A.y, 0.f);
            float e10 = fmaxf(uA.x + v1A.x, 0.f), e11 = fmaxf(uA.y + v1A.y, 0.f);
            float e20 = fmaxf(uB.x + v0B.x, 0.f), e21 = fmaxf(uB.y + v0B.y, 0.f);
            float e30 = fmaxf(uB.x + v1B.x, 0.f), e31 = fmaxf(uB.y + v1B.y, 0.f);
            u32 a0h = pk(e00, e01), a1h = pk(e10, e11);
            u32 a2h = pk(e20, e21), a3h = pk(e30, e31);
            u32 a0l = pk_res(e00, e01, a0h), a1l = pk_res(e10, e11, a1h);
            u32 a2l = pk_res(e20, e21, a2h), a3l = pk_res(e30, e31, a3h);
            #pragma unroll
            for (int nt = 0; nt < 8; nt++) {
                uint4 B = W2s[(ks * 8 + nt) * 32 + l];
                mma16(cA[nt], a0h, a1h, a2h, a3h, B.x, B.y);
                mma16(cA[nt], a0l, a1l, a2l, a3l, B.x, B.y);
                mma16(cA[nt], a0h, a1h, a2h, a3h, B.z, B.w);
            }
        }

        float cB[4][4];
        #pragma unroll
        for (int nt = 0; nt < 4; nt++)
            #pragma unroll
            for (int q = 0; q < 4; q++) cB[nt][q] = 0.f;

        #pragma unroll
        for (int ks = 0; ks < 4; ks++) {
            int n0 = 2 * ks, n1 = n0 + 1;
            float cb00 = c2s[8 * n0 + 2 * tg], cb01 = c2s[8 * n0 + 2 * tg + 1];
            float cb10 = c2s[8 * n1 + 2 * tg], cb11 = c2s[8 * n1 + 2 * tg + 1];
            float e00 = fmaxf(cA[n0][0] + cb00, 0.f), e01 = fmaxf(cA[n0][1] + cb01, 0.f);
            float e10 = fmaxf(cA[n0][2] + cb00, 0.f), e11 = fmaxf(cA[n0][3] + cb01, 0.f);
            float e20 = fmaxf(cA[n1][0] + cb10, 0.f), e21 = fmaxf(cA[n1][1] + cb11, 0.f);
            float e30 = fmaxf(cA[n1][2] + cb10, 0.f), e31 = fmaxf(cA[n1][3] + cb11, 0.f);
            u32 a0h = pk(e00, e01), a1h = pk(e10, e11);
            u32 a2h = pk(e20, e21), a3h = pk(e30, e31);
            u32 a0l = pk_res(e00, e01, a0h), a1l = pk_res(e10, e11, a1h);
            u32 a2l = pk_res(e20, e21, a2h), a3l = pk_res(e30, e31, a3h);
            #pragma unroll
            for (int nt = 0; nt < 4; nt++) {
                uint4 B = W3s[(ks * 4 + nt) * 32 + l];
                mma16(cB[nt], a0h, a1h, a2h, a3h, B.x, B.y);
                mma16(cB[nt], a0l, a1l, a2l, a3l, B.x, B.y);
                mma16(cB[nt], a0h, a1h, a2h, a3h, B.z, B.w);
            }
        }

        {
            float pl = 0.f, ph = 0.f;
            #pragma unroll
            for (int nt = 0; nt < 4; nt++) {
                int c0 = 8 * nt + 2 * tg, c1 = c0 + 1;
                float w0 = w4s[c0], w1 = w4s[c1];
                float b0 = c3s[c0], b1 = c3s[c1];
                pl += fmaxf(cB[nt][0] + b0, 0.f) * w0 + fmaxf(cB[nt][1] + b1, 0.f) * w1;
                ph += fmaxf(cB[nt][2] + b0, 0.f) * w0 + fmaxf(cB[nt][3] + b1, 0.f) * w1;
            }
            pl += __shfl_xor_sync(0xffffffffu, pl, 1);
            pl += __shfl_xor_sync(0xffffffffu, pl, 2);
            ph += __shfl_xor_sync(0xffffffffu, ph, 1);
            ph += __shfl_xor_sync(0xffffffffu, ph, 2);
            if (tg == 0) {
                float base = b4s[0];
                size_t row = ((size_t)b * NN + i0 + w) * NN + j0;
                g_L[row + gid]     = base + pl;
                g_L[row + gid + 8] = base + ph;
            }
        }
        // no end-of-loop sync: triple buffering tolerates 1-iteration warp skew
    }
}

// ---------------- epilogue: 64x64 tile, 512 threads, 2x4 outs/thread --------
__global__ __launch_bounds__(512)
void k_epi(const int* __restrict__ masks, float* __restrict__ out,
           int write_logits) {
    extern __shared__ __align__(16) char esm[];
    float* NFIT = (float*)(esm + EOFF_NFIT);
    float* NFJT = (float*)(esm + EOFF_NFJT);
    float* LIJ  = (float*)(esm + EOFF_LIJ);
    float* LJIT = (float*)(esm + EOFF_LJIT);
    int*   mI   = (int*)  (esm + EOFF_MI);
    int*   mJ   = (int*)  (esm + EOFF_MJ);
    int*   actp = (int*)  (esm + EOFF_ACT);

    int b  = blockIdx.z;
    int i0 = blockIdx.y * 64;
    int j0 = blockIdx.x * 64;
    int t  = threadIdx.x;

    {
        int rowt = t >> 4, colt = (t & 15) * 4;   // 512 threads: rowt 0..31
        #pragma unroll
        for (int it = 0; it < 2; it++) {
            int r = rowt + it * 32;
            float4 x = *(const float4*)&g_nfn[((size_t)b * NN + i0 + r) * DD + colt];
            NFIT[(colt + 0) * 68 + r] = x.x;
            NFIT[(colt + 1) * 68 + r] = x.y;
            NFIT[(colt + 2) * 68 + r] = x.z;
            NFIT[(colt + 3) * 68 + r] = x.w;
            float4 y = *(const float4*)&g_nfn[((size_t)b * NN + j0 + r) * DD + colt];
            NFJT[(colt + 0) * 68 + r] = y.x;
            NFJT[(colt + 1) * 68 + r] = y.y;
            NFJT[(colt + 2) * 68 + r] = y.z;
            NFJT[(colt + 3) * 68 + r] = y.w;
        }
        #pragma unroll
        for (int it = 0; it < 2; it++) {
            int r = rowt + it * 32;
            float4 L1 = *(const float4*)&g_L[((size_t)b * NN + i0 + r) * NN + j0 + colt];
            *(float4*)&LIJ[r * 68 + colt] = L1;
            float4 L2 = *(const float4*)&g_L[((size_t)b * NN + j0 + r) * NN + i0 + colt];
            LJIT[(colt + 0) * 68 + r] = L2.x;
            LJIT[(colt + 1) * 68 + r] = L2.y;
            LJIT[(colt + 2) * 68 + r] = L2.z;
            LJIT[(colt + 3) * 68 + r] = L2.w;
        }
        if (t < 64) mI[t] = masks[b * NN + i0 + t];
        else if (t < 128) mJ[t - 64] = masks[b * NN + j0 + (t - 64)];
        else if (t == 128) actp[0] = g_active[b];
    }
    __syncthreads();

    int ti = t >> 4;                // 0..31 -> 2 i rows
    int tj = t & 15;                // 0..15 -> 4 j cols

    float acc[2][4];
    #pragma unroll
    for (int r = 0; r < 2; r++)
        #pragma unroll
        for (int c = 0; c < 4; c++) acc[r][c] = 0.f;

    #pragma unroll 8
    for (int k = 0; k < DD; k++) {
        float2 ai = *(const float2*)&NFIT[k * 68 + ti * 2];
        float4 aj = *(const float4*)&NFJT[k * 68 + tj * 4];
        float ajr[4] = { aj.x, aj.y, aj.z, aj.w };
        #pragma unroll
        for (int c = 0; c < 4; c++) {
            acc[0][c] += ai.x * ajr[c];
            acc[1][c] += ai.y * ajr[c];
        }
    }

    int act = actp[0];
    #pragma unroll
    for (int r = 0; r < 2; r++) {
        int il = ti * 2 + r;
        int ig = i0 + il;
        float4 lx = *(const float4*)&LIJ [il * 68 + tj * 4];
        float4 ly = *(const float4*)&LJIT[il * 68 + tj * 4];
        float lij[4] = { lx.x, lx.y, lx.z, lx.w };
        float lji[4] = { ly.x, ly.y, ly.z, ly.w };
        float4 po, lo;
        float* pp = &po.x;
        float* ll = &lo.x;
        bool mi = (mI[il] != 0) && (act != 0);
        #pragma unroll
        for (int c = 0; c < 4; c++) {
            int jl = tj * 4 + c;
            int jg = j0 + jl;
            float lsym = (ig == jg) ? -10.f : 0.5f * (lij[c] + lji[c]);
            float logit = (lsym + 2.f * acc[r][c]) * 2.f;
            float p = 1.f / (1.f + __expf(-logit));
            p = (p > 0.6f) ? p * 1.2f : p * 0.8f;
            p = fminf(fmaxf(p, 0.f), 1.f);
            bool m = mi && (mJ[jl] != 0);
            pp[c] = m ? p : 0.f;
            ll[c] = m ? logit : 0.f;
        }
        size_t idx = ((size_t)b * NN + ig) * NN + j0 + tj * 4;
        *(float4*)&out[idx] = po;
        if (write_logits) *(float4*)&out[(size_t)BB * NN * NN + idx] = lo;
    }
}

// ---------------- launch ----------------
extern "C" void kernel_launch(void* const* d_in, const int* in_sizes, int n_in,
                              void* d_out, int out_size) {
    const float* nf    = (const float*)d_in[0];
    const int*   masks = (const int*)  d_in[1];
    const float *W1, *b1, *W2, *b2, *W3, *b3, *W4, *b4;
    const float *g1, *be1, *m1, *v1, *g2, *be2, *m2, *v2, *g3, *be3, *m3, *v3;

    if (n_in >= 22 && in_sizes[4] == 8192) {
        W1 = (const float*)d_in[2];  b1 = (const float*)d_in[3];
        W2 = (const float*)d_in[4];  b2 = (const float*)d_in[5];
        W3 = (const float*)d_in[6];  b3 = (const float*)d_in[7];
        W4 = (const float*)d_in[8];  b4 = (const float*)d_in[9];
        g1 = (const float*)d_in[10]; be1 = (const float*)d_in[11];
        m1 = (const float*)d_in[12]; v1  = (const float*)d_in[13];
        g2 = (const float*)d_in[14]; be2 = (const float*)d_in[15];
        m2 = (const float*)d_in[16]; v2  = (const float*)d_in[17];
        g3 = (const float*)d_in[18]; be3 = (const float*)d_in[19];
        m3 = (const float*)d_in[20]; v3  = (const float*)d_in[21];
    } else {
        W1 = (const float*)d_in[2];  b1 = (const float*)d_in[3];
        g1 = (const float*)d_in[4];  be1 = (const float*)d_in[5];
        m1 = (const float*)d_in[6];  v1  = (const float*)d_in[7];
        W2 = (const float*)d_in[8];  b2 = (const float*)d_in[9];
        g2 = (const float*)d_in[10]; be2 = (const float*)d_in[11];
        m2 = (const float*)d_in[12]; v2  = (const float*)d_in[13];
        W3 = (const float*)d_in[14]; b3 = (const float*)d_in[15];
        g3 = (const float*)d_in[16]; be3 = (const float*)d_in[17];
        m3 = (const float*)d_in[18]; v3  = (const float*)d_in[19];
        W4 = (const float*)d_in[20]; b4 = (const float*)d_in[21];
    }

    static bool attr_set = false;
    if (!attr_set) {
        cudaFuncSetAttribute(k_main_mma, cudaFuncAttributeMaxDynamicSharedMemorySize, SMEM_MM);
        cudaFuncSetAttribute(k_epi, cudaFuncAttributeMaxDynamicSharedMemorySize, SMEM_EPI);
        attr_set = true;
    }

    k_setup<<<26, 256>>>(W1, b1, g1, be1, m1, v1,
                         W2, b2, g2, be2, m2, v2,
                         W3, b3, g3, be3, m3, v3, W4, b4, masks);
    k_nodes<<<BB * NN / 8, 128>>>(nf);
    k_main_mma<<<296, 256, SMEM_MM>>>();
    int wl = (out_size >= 2 * BB * NN * NN) ? 1 : 0;
    k_epi<<<dim3(NN / 64, NN / 64, BB), 512, SMEM_EPI>>>(masks, (float*)d_out, wl);
}

// round 16
// speedup vs baseline: 1.0991x; 1.0991x over previous
#include <cuda_runtime.h>
#include <cuda_bf16.h>
#include <cstdint>
#include <math.h>

#define EPS   1e-5f
#define BB    2
#define NN    512
#define DD    64

typedef unsigned long long ull;
typedef unsigned int u32;

// ---------------- device scratch ----------------
__device__ __align__(16) float g_U   [BB*NN*128];
__device__ __align__(16) float g_V   [BB*NN*128];
__device__ __align__(16) float g_nfn [BB*NN*DD];
__device__ __align__(16) float g_W1t [128*128];
__device__ __align__(16) float g_Vb1 [128];
__device__ __align__(16) uint4 g_W2f [8*8*32];
__device__ __align__(16) uint4 g_W3f [4*4*32];
__device__ float g_c2[64], g_c3[32], g_w4[32], g_b4s;
__device__ __align__(16) float g_L   [BB*NN*NN];
__device__ int   g_active[BB];

// ---------------- helpers ----------------
__device__ __forceinline__ u32 pk(float e0, float e1) {
    u32 r; asm("cvt.rn.bf16x2.f32 %0, %1, %2;" : "=r"(r) : "f"(e1), "f"(e0)); return r;
}
__device__ __forceinline__ u32 pk_res(float e0, float e1, u32 h) {
    float r0 = __uint_as_float(h << 16);
    float r1 = __uint_as_float(h & 0xffff0000u);
    return pk(e0 - r0, e1 - r1);
}
__device__ __forceinline__ void mma16(float c[4], u32 a0, u32 a1, u32 a2, u32 a3,
                                      u32 b0, u32 b1) {
    asm("mma.sync.aligned.m16n8k16.row.col.f32.bf16.bf16.f32 "
        "{%0,%1,%2,%3}, {%4,%5,%6,%7}, {%8,%9}, {%0,%1,%2,%3};"
        : "+f"(c[0]), "+f"(c[1]), "+f"(c[2]), "+f"(c[3])
        : "r"(a0), "r"(a1), "r"(a2), "r"(a3), "r"(b0), "r"(b1));
}
__device__ __forceinline__ u32 s2u(const void* p) {
    u32 a;
    asm("{ .reg .u64 t; cvta.to.shared.u64 t, %1; cvt.u32.u64 %0, t; }" : "=r"(a) : "l"(p));
    return a;
}
__device__ __forceinline__ void cp16(u32 dst, const void* src) {
    asm volatile("cp.async.ca.shared.global [%0], [%1], 16;"
                 :: "r"(dst), "l"(__cvta_generic_to_global(src)) : "memory");
}
#define CP_COMMIT() asm volatile("cp.async.commit_group;" ::: "memory")
#define CP_WAIT(n)  asm volatile("cp.async.wait_group %0;" :: "n"(n) : "memory")

// ---------------- smem layout for k_main (bytes) ----------------
#define OFF_W2F  0          /* 32768 */
#define OFF_W3F  32768      /* 8192 */
#define OFF_US   40960      /* 3 x 4096 (8*128 f32)  */
#define OFF_VS   53248      /* 3 x 8448 (16*132 f32) */
#define OFF_C2   78592      /* 256 */
#define OFF_C3   78848      /* 128 */
#define OFF_W4   78976      /* 128 */
#define OFF_B4   79104      /* 4 */
#define SMEM_MM  79120

// ---------------- smem layout for k_epi (bytes) ----------------
#define EOFF_NFIT  0                    /* 64*68 f32 = 17408 B */
#define EOFF_NFJT  17408
#define EOFF_LIJ   34816
#define EOFF_LJIT  52224
#define EOFF_MI    69632               /* 64 ints */
#define EOFF_MJ    69888
#define EOFF_ACT   70144
#define SMEM_EPI   70160

// ---------------- setup: W1 transpose+fold, frag packing, consts, active ---
__global__ void k_setup(const float* __restrict__ W1, const float* __restrict__ b1,
                        const float* __restrict__ g1, const float* __restrict__ be1,
                        const float* __restrict__ m1, const float* __restrict__ v1,
                        const float* __restrict__ W2, const float* __restrict__ b2,
                        const float* __restrict__ g2, const float* __restrict__ be2,
                        const float* __restrict__ m2, const float* __restrict__ v2,
                        const float* __restrict__ W3, const float* __restrict__ b3,
                        const float* __restrict__ g3, const float* __restrict__ be3,
                        const float* __restrict__ m3, const float* __restrict__ v3,
                        const float* __restrict__ W4, const float* __restrict__ b4,
                        const int* __restrict__ masks) {
    int t = threadIdx.x;
    int bid = blockIdx.x;
    if (bid < 16) {
        __shared__ float tile[32][33];
        int ti = bid >> 2, tj = bid & 3;
        int tx = t & 31, ty = t >> 5;
        #pragma unroll
        for (int r = 0; r < 4; r++) {
            int o = ti * 32 + ty + 8 * r, in = tj * 32 + tx;
            tile[ty + 8 * r][tx] = W1[o * 128 + in];
        }
        __syncthreads();
        int o2 = ti * 32 + tx;
        float s1 = g1[o2] * rsqrtf(v1[o2] + EPS);
        #pragma unroll
        for (int r = 0; r < 4; r++) {
            int in2 = tj * 32 + ty + 8 * r;
            g_W1t[in2 * 128 + o2] = tile[tx][ty + 8 * r] * s1;
        }
        return;
    }
    if (bid < 24) {
        int fb = bid - 16;
        int idx = fb * 256 + t;
        {
            int ks = idx >> 8, nt = (idx >> 5) & 7, l = idx & 31;
            int n = 8 * nt + (l >> 2), k0 = 16 * ks + 2 * (l & 3);
            float s = g2[n] * rsqrtf(v2[n] + EPS);
            float w00 = W2[n * 128 + k0] * s,     w01 = W2[n * 128 + k0 + 1] * s;
            float w10 = W2[n * 128 + k0 + 8] * s, w11 = W2[n * 128 + k0 + 9] * s;
            u32 bh0 = pk(w00, w01), bh1 = pk(w10, w11);
            g_W2f[idx] = make_uint4(bh0, bh1, pk_res(w00, w01, bh0), pk_res(w10, w11, bh1));
        }
        if (idx < 4 * 4 * 32) {
            int ks = idx >> 7, nt = (idx >> 5) & 3, l = idx & 31;
            int n = 8 * nt + (l >> 2), k0 = 16 * ks + 2 * (l & 3);
            float s = g3[n] * rsqrtf(v3[n] + EPS);
            float w00 = W3[n * 64 + k0] * s,     w01 = W3[n * 64 + k0 + 1] * s;
            float w10 = W3[n * 64 + k0 + 8] * s, w11 = W3[n * 64 + k0 + 9] * s;
            u32 bh0 = pk(w00, w01), bh1 = pk(w10, w11);
            g_W3f[idx] = make_uint4(bh0, bh1, pk_res(w00, w01, bh0), pk_res(w10, w11, bh1));
        }
        return;
    }
    if (bid == 24) {
        if (t < 128) {
            float s1 = g1[t] * rsqrtf(v1[t] + EPS);
            g_Vb1[t] = (b1[t] - m1[t]) * s1 + be1[t];
        } else if (t < 192) {
            int o = t - 128;
            float s = g2[o] * rsqrtf(v2[o] + EPS);
            g_c2[o] = (b2[o] - m2[o]) * s + be2[o];
        } else if (t < 224) {
            int o = t - 192;
            float s = g3[o] * rsqrtf(v3[o] + EPS);
            g_c3[o] = (b3[o] - m3[o]) * s + be3[o];
        } else {
            g_w4[t - 224] = W4[t - 224];
        }
        if (t == 0) g_b4s = b4[0];
        return;
    }
    {
        __shared__ int cnt[BB];
        if (t < BB) cnt[t] = 0;
        __syncthreads();
        for (int idx = t; idx < BB * NN; idx += 256)
            if (masks[idx] != 0) atomicAdd(&cnt[idx / NN], 1);
        __syncthreads();
        if (t < BB) g_active[t] = (cnt[t] > 1) ? 1 : 0;
    }
}

// ---------------- nodes: per-node U, V, normalized features ----------------
__global__ void k_nodes(const float* __restrict__ f) {
    __shared__ float fs[DD];
    __shared__ float sinv;
    int node = blockIdx.x;
    int t = threadIdx.x;
    if (t < DD) fs[t] = f[node * DD + t];
    __syncthreads();
    if (t < 32) {
        float a = fs[t], b = fs[t + 32];
        float ss = a * a + b * b;
        ss += __shfl_xor_sync(0xffffffffu, ss, 16);
        ss += __shfl_xor_sync(0xffffffffu, ss, 8);
        ss += __shfl_xor_sync(0xffffffffu, ss, 4);
        ss += __shfl_xor_sync(0xffffffffu, ss, 2);
        ss += __shfl_xor_sync(0xffffffffu, ss, 1);
        if (t == 0) sinv = 1.f / fmaxf(sqrtf(ss), 1e-12f);
    }
    __syncthreads();
    if (t < DD) g_nfn[node * DD + t] = fs[t] * sinv;

    float u = 0.f, vv = 0.f;
    #pragma unroll 8
    for (int d = 0; d < DD; d++) {
        float fd = fs[d];
        u  += g_W1t[d * 128 + t] * fd;
        vv += g_W1t[(d + DD) * 128 + t] * fd;
    }
    g_U[node * 128 + t] = u;
    g_V[node * 128 + t] = vv + g_Vb1[t];
}

// ---------------- main: fused MLP via mma.sync bf16 k16, triple-buffered ---
__global__ __launch_bounds__(256, 2)
void k_main_mma() {
    extern __shared__ __align__(16) char sm[];
    uint4* W2s = (uint4*)(sm + OFF_W2F);
    uint4* W3s = (uint4*)(sm + OFF_W3F);
    float* c2s = (float*)(sm + OFF_C2);
    float* c3s = (float*)(sm + OFF_C3);
    float* w4s = (float*)(sm + OFF_W4);
    float* b4s = (float*)(sm + OFF_B4);

    u32 smb = s2u(sm);
    int t = threadIdx.x;
    int w = t >> 5, l = t & 31;
    int tg = l & 3, gid = l >> 2;

    {
        const uint4* s4 = (const uint4*)g_W2f;
        for (int i = t; i < 8 * 8 * 32; i += 256) W2s[i] = s4[i];
        const uint4* s3 = (const uint4*)g_W3f;
        for (int i = t; i < 4 * 4 * 32; i += 256) W3s[i] = s3[i];
        if (t < 64) c2s[t] = g_c2[t];
        if (t < 32) { c3s[t] = g_c3[t]; w4s[t] = g_w4[t]; }
        if (t == 0) b4s[0] = g_b4s;
    }

    const int NT = BB * (NN / 8) * (NN / 16);
    const int gsz = gridDim.x;

    auto stage = [&](int tile, int buf) {
        int b   = tile >> 11;
        int rem = tile & 2047;
        int i0  = (rem >> 5) << 3;
        int j0  = (rem & 31) << 4;
        cp16(smb + OFF_US + buf * 4096 + t * 16,
             (const char*)&g_U[((size_t)b * NN + i0) * 128] + t * 16);
        #pragma unroll
        for (int q = 0; q < 2; q++) {
            int c = t + q * 256;
            int jj = c >> 5, kq = c & 31;
            cp16(smb + OFF_VS + buf * 8448 + (jj * 132 + kq * 4) * 4,
                 &g_V[((size_t)b * NN + j0 + jj) * 128 + kq * 4]);
        }
        CP_COMMIT();
    };

    int first = blockIdx.x;
    if (first < NT) stage(first, 0);

    int pidx = 0;
    for (int tile = first; tile < NT; tile += gsz) {
        int nxt = tile + gsz;
        int nbuf = (pidx == 2) ? 0 : pidx + 1;
        if (nxt < NT) { stage(nxt, nbuf); CP_WAIT(1); }
        else          { CP_WAIT(0); }
        __syncthreads();

        float* Us = (float*)(sm + OFF_US + pidx * 4096);
        float* Vs = (float*)(sm + OFF_VS + pidx * 8448);
        pidx = nbuf;

        int b   = tile >> 11;
        int rem = tile & 2047;
        int i0  = (rem >> 5) << 3;
        int j0  = (rem & 31) << 4;

        float cA[8][4];
        #pragma unroll
        for (int nt = 0; nt < 8; nt++)
            #pragma unroll
            for (int q = 0; q < 4; q++) cA[nt][q] = 0.f;

        const float* urow = &Us[w * 128];
        #pragma unroll
        for (int ks = 0; ks < 8; ks++) {
            int k0 = 16 * ks + 2 * tg;
            float2 uA  = *(const float2*)&urow[k0];
            float2 uB  = *(const float2*)&urow[k0 + 8];
            float2 v0A = *(const float2*)&Vs[gid * 132 + k0];
            float2 v1A = *(const float2*)&Vs[(gid + 8) * 132 + k0];
            float2 v0B = *(const float2*)&Vs[gid * 132 + k0 + 8];
            float2 v1B = *(const float2*)&Vs[(gid + 8) * 132 + k0 + 8];
            float e00 = fmaxf(uA.x + v0A.x, 0.f), e01 = fmaxf(uA.y + v0A.y, 0.f);
            float e10 = fmaxf(uA.x + v1A.x, 0.f), e11 = fmaxf(uA.y + v1A.y, 0.f);
            float e20 = fmaxf(uB.x + v0B.x, 0.f), e21 = fmaxf(uB.y + v0B.y, 0.f);
            float e30 = fmaxf(uB.x + v1B.x, 0.f), e31 = fmaxf(uB.y + v1B.y, 0.f);
            u32 a0h = pk(e00, e01), a1h = pk(e10, e11);
            u32 a2h = pk(e20, e21), a3h = pk(e30, e31);
            u32 a0l = pk_res(e00, e01, a0h), a1l = pk_res(e10, e11, a1h);
            u32 a2l = pk_res(e20, e21, a2h), a3l = pk_res(e30, e31, a3h);
            #pragma unroll
            for (int nt = 0; nt < 8; nt++) {
                uint4 B = W2s[(ks * 8 + nt) * 32 + l];
                mma16(cA[nt], a0h, a1h, a2h, a3h, B.x, B.y);
                mma16(cA[nt], a0l, a1l, a2l, a3l, B.x, B.y);
                mma16(cA[nt], a0h, a1h, a2h, a3h, B.z, B.w);
            }
        }

        float cB[4][4];
        #pragma unroll
        for (int nt = 0; nt < 4; nt++)
            #pragma unroll
            for (int q = 0; q < 4; q++) cB[nt][q] = 0.f;

        #pragma unroll
        for (int ks = 0; ks < 4; ks++) {
            int n0 = 2 * ks, n1 = n0 + 1;
            float cb00 = c2s[8 * n0 + 2 * tg], cb01 = c2s[8 * n0 + 2 * tg + 1];
            float cb10 = c2s[8 * n1 + 2 * tg], cb11 = c2s[8 * n1 + 2 * tg + 1];
            float e00 = fmaxf(cA[n0][0] + cb00, 0.f), e01 = fmaxf(cA[n0][1] + cb01, 0.f);
            float e10 = fmaxf(cA[n0][2] + cb00, 0.f), e11 = fmaxf(cA[n0][3] + cb01, 0.f);
            float e20 = fmaxf(cA[n1][0] + cb10, 0.f), e21 = fmaxf(cA[n1][1] + cb11, 0.f);
            float e30 = fmaxf(cA[n1][2] + cb10, 0.f), e31 = fmaxf(cA[n1][3] + cb11, 0.f);
            u32 a0h = pk(e00, e01), a1h = pk(e10, e11);
            u32 a2h = pk(e20, e21), a3h = pk(e30, e31);
            u32 a0l = pk_res(e00, e01, a0h), a1l = pk_res(e10, e11, a1h);
            u32 a2l = pk_res(e20, e21, a2h), a3l = pk_res(e30, e31, a3h);
            #pragma unroll
            for (int nt = 0; nt < 4; nt++) {
                uint4 B = W3s[(ks * 4 + nt) * 32 + l];
                mma16(cB[nt], a0h, a1h, a2h, a3h, B.x, B.y);
                mma16(cB[nt], a0l, a1l, a2l, a3l, B.x, B.y);
                mma16(cB[nt], a0h, a1h, a2h, a3h, B.z, B.w);
            }
        }

        {
            float pl = 0.f, ph = 0.f;
            #pragma unroll
            for (int nt = 0; nt < 4; nt++) {
                int c0 = 8 * nt + 2 * tg, c1 = c0 + 1;
                float w0 = w4s[c0], w1 = w4s[c1];
                float b0 = c3s[c0], b1 = c3s[c1];
                pl += fmaxf(cB[nt][0] + b0, 0.f) * w0 + fmaxf(cB[nt][1] + b1, 0.f) * w1;
                ph += fmaxf(cB[nt][2] + b0, 0.f) * w0 + fmaxf(cB[nt][3] + b1, 0.f) * w1;
            }
            pl += __shfl_xor_sync(0xffffffffu, pl, 1);
            pl += __shfl_xor_sync(0xffffffffu, pl, 2);
            ph += __shfl_xor_sync(0xffffffffu, ph, 1);
            ph += __shfl_xor_sync(0xffffffffu, ph, 2);
            if (tg == 0) {
                float base = b4s[0];
                size_t row = ((size_t)b * NN + i0 + w) * NN + j0;
                g_L[row + gid]     = base + pl;
                g_L[row + gid + 8] = base + ph;
            }
        }
        // no end-of-loop sync: triple buffering tolerates 1-iteration warp skew
    }
}

// ---------------- epilogue: 64x64 register-blocked sym+sim+sigmoid+mask -----
__global__ __launch_bounds__(256)
void k_epi(const int* __restrict__ masks, float* __restrict__ out,
           int write_logits) {
    extern __shared__ __align__(16) char esm[];
    float* NFIT = (float*)(esm + EOFF_NFIT);
    float* NFJT = (float*)(esm + EOFF_NFJT);
    float* LIJ  = (float*)(esm + EOFF_LIJ);
    float* LJIT = (float*)(esm + EOFF_LJIT);
    int*   mI   = (int*)  (esm + EOFF_MI);
    int*   mJ   = (int*)  (esm + EOFF_MJ);
    int*   actp = (int*)  (esm + EOFF_ACT);

    int b  = blockIdx.z;
    int i0 = blockIdx.y * 64;
    int j0 = blockIdx.x * 64;
    int t  = threadIdx.x;
    int rowt = t >> 4;
    int colt = (t & 15) * 4;

    #pragma unroll
    for (int it = 0; it < 4; it++) {
        int r = rowt + it * 16;
        float4 x = *(const float4*)&g_nfn[((size_t)b * NN + i0 + r) * DD + colt];
        NFIT[(colt + 0) * 68 + r] = x.x;
        NFIT[(colt + 1) * 68 + r] = x.y;
        NFIT[(colt + 2) * 68 + r] = x.z;
        NFIT[(colt + 3) * 68 + r] = x.w;
        float4 y = *(const float4*)&g_nfn[((size_t)b * NN + j0 + r) * DD + colt];
        NFJT[(colt + 0) * 68 + r] = y.x;
        NFJT[(colt + 1) * 68 + r] = y.y;
        NFJT[(colt + 2) * 68 + r] = y.z;
        NFJT[(colt + 3) * 68 + r] = y.w;
    }
    #pragma unroll
    for (int it = 0; it < 4; it++) {
        int r = rowt + it * 16;
        float4 L1 = *(const float4*)&g_L[((size_t)b * NN + i0 + r) * NN + j0 + colt];
        *(float4*)&LIJ[r * 68 + colt] = L1;
        float4 L2 = *(const float4*)&g_L[((size_t)b * NN + j0 + r) * NN + i0 + colt];
        LJIT[(colt + 0) * 68 + r] = L2.x;
        LJIT[(colt + 1) * 68 + r] = L2.y;
        LJIT[(colt + 2) * 68 + r] = L2.z;
        LJIT[(colt + 3) * 68 + r] = L2.w;
    }
    if (t < 64) mI[t] = masks[b * NN + i0 + t];
    else if (t < 128) mJ[t - 64] = masks[b * NN + j0 + (t - 64)];
    else if (t == 128) actp[0] = g_active[b];
    __syncthreads();

    int ti = t >> 4;
    int tj = t & 15;

    float acc[4][4];
    #pragma unroll
    for (int r = 0; r < 4; r++)
        #pragma unroll
        for (int c = 0; c < 4; c++) acc[r][c] = 0.f;

    #pragma unroll 8
    for (int k = 0; k < DD; k++) {
        float4 ai = *(const float4*)&NFIT[k * 68 + ti * 4];
        float4 aj = *(const float4*)&NFJT[k * 68 + tj * 4];
        float air[4] = { ai.x, ai.y, ai.z, ai.w };
        float ajr[4] = { aj.x, aj.y, aj.z, aj.w };
        #pragma unroll
        for (int r = 0; r < 4; r++)
            #pragma unroll
            for (int c = 0; c < 4; c++) acc[r][c] += air[r] * ajr[c];
    }

    int act = actp[0];
    #pragma unroll
    for (int r = 0; r < 4; r++) {
        int il = ti * 4 + r;
        int ig = i0 + il;
        float4 lx = *(const float4*)&LIJ [il * 68 + tj * 4];
        float4 ly = *(const float4*)&LJIT[il * 68 + tj * 4];
        float lij[4] = { lx.x, lx.y, lx.z, lx.w };
        float lji[4] = { ly.x, ly.y, ly.z, ly.w };
        float4 po, lo;
        float* pp = &po.x;
        float* ll = &lo.x;
        bool mi = (mI[il] != 0) && (act != 0);
        #pragma unroll
        for (int c = 0; c < 4; c++) {
            int jl = tj * 4 + c;
            int jg = j0 + jl;
            float lsym = (ig == jg) ? -10.f : 0.5f * (lij[c] + lji[c]);
            float logit = (lsym + 2.f * acc[r][c]) * 2.f;
            float p = 1.f / (1.f + expf(-logit));
            p = (p > 0.6f) ? p * 1.2f : p * 0.8f;
            p = fminf(fmaxf(p, 0.f), 1.f);
            bool m = mi && (mJ[jl] != 0);
            pp[c] = m ? p : 0.f;
            ll[c] = m ? logit : 0.f;
        }
        size_t idx = ((size_t)b * NN + ig) * NN + j0 + tj * 4;
        *(float4*)&out[idx] = po;
        if (write_logits) *(float4*)&out[(size_t)BB * NN * NN + idx] = lo;
    }
}

// ---------------- launch ----------------
extern "C" void kernel_launch(void* const* d_in, const int* in_sizes, int n_in,
                              void* d_out, int out_size) {
    const float* nf    = (const float*)d_in[0];
    const int*   masks = (const int*)  d_in[1];
    const float *W1, *b1, *W2, *b2, *W3, *b3, *W4, *b4;
    const float *g1, *be1, *m1, *v1, *g2, *be2, *m2, *v2, *g3, *be3, *m3, *v3;

    if (n_in >= 22 && in_sizes[4] == 8192) {
        W1 = (const float*)d_in[2];  b1 = (const float*)d_in[3];
        W2 = (const float*)d_in[4];  b2 = (const float*)d_in[5];
        W3 = (const float*)d_in[6];  b3 = (const float*)d_in[7];
        W4 = (const float*)d_in[8];  b4 = (const float*)d_in[9];
        g1 = (const float*)d_in[10]; be1 = (const float*)d_in[11];
        m1 = (const float*)d_in[12]; v1  = (const float*)d_in[13];
        g2 = (const float*)d_in[14]; be2 = (const float*)d_in[15];
        m2 = (const float*)d_in[16]; v2  = (const float*)d_in[17];
        g3 = (const float*)d_in[18]; be3 = (const float*)d_in[19];
        m3 = (const float*)d_in[20]; v3  = (const float*)d_in[21];
    } else {
        W1 = (const float*)d_in[2];  b1 = (const float*)d_in[3];
        g1 = (const float*)d_in[4];  be1 = (const float*)d_in[5];
        m1 = (const float*)d_in[6];  v1  = (const float*)d_in[7];
        W2 = (const float*)d_in[8];  b2 = (const float*)d_in[9];
        g2 = (const float*)d_in[10]; be2 = (const float*)d_in[11];
        m2 = (const float*)d_in[12]; v2  = (const float*)d_in[13];
        W3 = (const float*)d_in[14]; b3 = (const float*)d_in[15];
        g3 = (const float*)d_in[16]; be3 = (const float*)d_in[17];
        m3 = (const float*)d_in[18]; v3  = (const float*)d_in[19];
        W4 = (const float*)d_in[20]; b4 = (const float*)d_in[21];
    }

    static bool attr_set = false;
    if (!attr_set) {
        cudaFuncSetAttribute(k_main_mma, cudaFuncAttributeMaxDynamicSharedMemorySize, SMEM_MM);
        cudaFuncSetAttribute(k_epi, cudaFuncAttributeMaxDynamicSharedMemorySize, SMEM_EPI);
        attr_set = true;
    }

    k_setup<<<26, 256>>>(W1, b1, g1, be1, m1, v1,
                         W2, b2, g2, be2, m2, v2,
                         W3, b3, g3, be3, m3, v3, W4, b4, masks);
    k_nodes<<<BB * NN, 128>>>(nf);
    k_main_mma<<<296, 256, SMEM_MM>>>();
    int wl = (out_size >= 2 * BB * NN * NN) ? 1 : 0;
    k_epi<<<dim3(NN / 64, NN / 64, BB), 256, SMEM_EPI>>>(masks, (float*)d_out, wl);
}